// round 3
// baseline (speedup 1.0000x reference)
#include <cuda_runtime.h>
#include <cuda_bf16.h>
#include <math.h>

// Problem constants (fixed by the reference)
#define NN 50000
#define EE 400000
// IN=128, H1=128, HEADS=8, HID=16, OUT=128, EDIM=32

// ---------------- scratch (static device globals; no allocation) -------------
static __device__ float g_Q[NN * 128];
static __device__ float g_K[NN * 128];
static __device__ float g_V[NN * 128];
static __device__ float g_H[NN * 128];          // layer1 accumulator -> h
static __device__ float g_E1[(size_t)EE * 128]; // edge embedding (per layer, reused)
static __device__ float g_EA[EE * 8];           // exp(alpha) per edge (layer1: 8 heads, layer2: 1)
static __device__ float g_D[NN * 8 + NN];       // softmax denominators (layer1: N*8, layer2: N)
static __device__ int   g_src[EE];
static __device__ int   g_dst[EE];
static __device__ int   g_is64;

// ---------------- dtype sniffing for edge_index ------------------------------
// Reference requests int64, but default JAX silently yields int32. If the data
// is int64 (values < 50000), every odd 32-bit word is zero.
__global__ void detect_idx_kernel(const unsigned int* __restrict__ p) {
    __shared__ unsigned int sh[256];
    unsigned int acc = 0;
    for (int i = threadIdx.x; i < 4096; i += 256) acc |= p[2 * i + 1];
    sh[threadIdx.x] = acc;
    __syncthreads();
    for (int s = 128; s > 0; s >>= 1) {
        if (threadIdx.x < s) sh[threadIdx.x] |= sh[threadIdx.x + s];
        __syncthreads();
    }
    if (threadIdx.x == 0) g_is64 = (sh[0] == 0u) ? 1 : 0;
}

__global__ void extract_idx_kernel(const void* __restrict__ p) {
    int e = blockIdx.x * blockDim.x + threadIdx.x;
    if (e >= EE) return;
    if (g_is64) {
        const long long* q = (const long long*)p;
        g_src[e] = (int)q[e];
        g_dst[e] = (int)q[EE + e];
    } else {
        const int* q = (const int*)p;
        g_src[e] = q[e];
        g_dst[e] = q[EE + e];
    }
}

__global__ void zero_denoms_kernel() {
    int i = blockIdx.x * blockDim.x + threadIdx.x;
    if (i < NN * 8 + NN) g_D[i] = 0.0f;
}

// ---------------- node GEMM: C[n,128] = A[n,128] @ W[128,128] + bias ---------
// 32-row tile, full 128 cols, 256 threads; each thread: 8 rows x 2 cols.
__global__ void __launch_bounds__(256) gemm128_kernel(
    const float* __restrict__ A, const float* __restrict__ W,
    const float* __restrict__ bias, float* __restrict__ C, int n)
{
    __shared__ float4 xs4[32][32];
    float* xs = (float*)xs4;
    int tid = threadIdx.x;
    int row0 = blockIdx.x * 32;

    for (int i = tid; i < 32 * 32; i += 256) {
        int r = i >> 5, c4 = i & 31;
        float4 v = make_float4(0.f, 0.f, 0.f, 0.f);
        if (row0 + r < n)
            v = reinterpret_cast<const float4*>(A + (size_t)(row0 + r) * 128)[c4];
        xs4[r][c4] = v;
    }
    __syncthreads();

    int j = tid & 63;
    int g = tid >> 6; // 0..3 -> rows g*8 .. g*8+7
    float b0 = bias ? bias[j] : 0.f;
    float b1 = bias ? bias[j + 64] : 0.f;
    float acc0[8], acc1[8];
#pragma unroll
    for (int r = 0; r < 8; r++) { acc0[r] = b0; acc1[r] = b1; }

    for (int i = 0; i < 128; i++) {
        float w0 = W[i * 128 + j];
        float w1 = W[i * 128 + j + 64];
#pragma unroll
        for (int r = 0; r < 8; r++) {
            float xv = xs[(g * 8 + r) * 128 + i];
            acc0[r] += xv * w0;
            acc1[r] += xv * w1;
        }
    }
#pragma unroll
    for (int r = 0; r < 8; r++) {
        int row = row0 + g * 8 + r;
        if (row < n) {
            C[(size_t)row * 128 + j]      = acc0[r];
            C[(size_t)row * 128 + j + 64] = acc1[r];
        }
    }
}

// ---------------- edge GEMM: C[E,128] = A[E,32] @ W[32,128] ------------------
__global__ void __launch_bounds__(256) gemm_edge_kernel(
    const float* __restrict__ A, const float* __restrict__ W, float* __restrict__ C)
{
    __shared__ float4 xs4[32][8];
    float* xs = (float*)xs4;
    int tid = threadIdx.x;
    int e0 = blockIdx.x * 32;

    for (int i = tid; i < 32 * 8; i += 256) {
        int r = i >> 3, c4 = i & 7;
        xs4[r][c4] = reinterpret_cast<const float4*>(A + (size_t)(e0 + r) * 32)[c4];
    }
    __syncthreads();

    int j = tid & 63;
    int g = tid >> 6;
    float acc0[8], acc1[8];
#pragma unroll
    for (int r = 0; r < 8; r++) { acc0[r] = 0.f; acc1[r] = 0.f; }

    for (int i = 0; i < 32; i++) {
        float w0 = W[i * 128 + j];
        float w1 = W[i * 128 + j + 64];
#pragma unroll
        for (int r = 0; r < 8; r++) {
            float xv = xs[(g * 8 + r) * 32 + i];
            acc0[r] += xv * w0;
            acc1[r] += xv * w1;
        }
    }
#pragma unroll
    for (int r = 0; r < 8; r++) {
        size_t e = (size_t)(e0 + g * 8 + r);
        C[e * 128 + j]      = acc0[r];
        C[e * 128 + j + 64] = acc1[r];
    }
}

// ---------------- layer 1 edge pass 1: ea + denom ----------------------------
// warp per edge; lane l handles float4 at offset l*4 (head = l/4)
__global__ void __launch_bounds__(256) epass1_l1_kernel() {
    int e = (blockIdx.x * blockDim.x + threadIdx.x) >> 5;
    if (e >= EE) return;
    int l = threadIdx.x & 31;
    int src = g_src[e], dst = g_dst[e];

    float4 q  = reinterpret_cast<const float4*>(g_Q + (size_t)dst * 128)[l];
    float4 k  = reinterpret_cast<const float4*>(g_K + (size_t)src * 128)[l];
    float4 ee = reinterpret_cast<const float4*>(g_E1 + (size_t)e * 128)[l];
    float p = q.x * (k.x + ee.x) + q.y * (k.y + ee.y)
            + q.z * (k.z + ee.z) + q.w * (k.w + ee.w);
    p += __shfl_xor_sync(0xffffffffu, p, 1);
    p += __shfl_xor_sync(0xffffffffu, p, 2);
    if ((l & 3) == 0) {
        int h = l >> 2;
        float ea = expf(p * 0.25f); // /sqrt(16)
        g_EA[e * 8 + h] = ea;
        atomicAdd(&g_D[dst * 8 + h], ea);
    }
}

// ---------------- layer 1 edge pass 2: scatter attn * (v + ee) ---------------
__global__ void __launch_bounds__(256) epass2_l1_kernel() {
    int e = (blockIdx.x * blockDim.x + threadIdx.x) >> 5;
    if (e >= EE) return;
    int l = threadIdx.x & 31;
    int src = g_src[e], dst = g_dst[e];
    int h = l >> 2;

    float att = 0.f;
    if ((l & 3) == 0)
        att = g_EA[e * 8 + h] / fmaxf(g_D[dst * 8 + h], 1e-16f);
    att = __shfl_sync(0xffffffffu, att, l & ~3);

    float4 v  = reinterpret_cast<const float4*>(g_V + (size_t)src * 128)[l];
    float4 ee = reinterpret_cast<const float4*>(g_E1 + (size_t)e * 128)[l];
    float* dp = g_H + (size_t)dst * 128 + l * 4;
    atomicAdd(dp + 0, att * (v.x + ee.x));
    atomicAdd(dp + 1, att * (v.y + ee.y));
    atomicAdd(dp + 2, att * (v.z + ee.z));
    atomicAdd(dp + 3, att * (v.w + ee.w));
}

// ---------------- layer 2 edge pass 1 (heads=1, ch=128) ----------------------
__global__ void __launch_bounds__(256) epass1_l2_kernel() {
    int e = (blockIdx.x * blockDim.x + threadIdx.x) >> 5;
    if (e >= EE) return;
    int l = threadIdx.x & 31;
    int src = g_src[e], dst = g_dst[e];

    float4 q  = reinterpret_cast<const float4*>(g_Q + (size_t)dst * 128)[l];
    float4 k  = reinterpret_cast<const float4*>(g_K + (size_t)src * 128)[l];
    float4 ee = reinterpret_cast<const float4*>(g_E1 + (size_t)e * 128)[l];
    float p = q.x * (k.x + ee.x) + q.y * (k.y + ee.y)
            + q.z * (k.z + ee.z) + q.w * (k.w + ee.w);
#pragma unroll
    for (int off = 16; off > 0; off >>= 1) p += __shfl_xor_sync(0xffffffffu, p, off);
    if (l == 0) {
        float ea = expf(p * 0.08838834764831845f); // /sqrt(128)
        g_EA[e] = ea;
        atomicAdd(&g_D[NN * 8 + dst], ea);
    }
}

// ---------------- layer 2 edge pass 2 ----------------------------------------
__global__ void __launch_bounds__(256) epass2_l2_kernel(float* __restrict__ out) {
    int e = (blockIdx.x * blockDim.x + threadIdx.x) >> 5;
    if (e >= EE) return;
    int l = threadIdx.x & 31;
    int src = g_src[e], dst = g_dst[e];

    float att = 0.f;
    if (l == 0) att = g_EA[e] / fmaxf(g_D[NN * 8 + dst], 1e-16f);
    att = __shfl_sync(0xffffffffu, att, 0);

    float4 v  = reinterpret_cast<const float4*>(g_V + (size_t)src * 128)[l];
    float4 ee = reinterpret_cast<const float4*>(g_E1 + (size_t)e * 128)[l];
    float* dp = out + (size_t)dst * 128 + l * 4;
    atomicAdd(dp + 0, att * (v.x + ee.x));
    atomicAdd(dp + 1, att * (v.y + ee.y));
    atomicAdd(dp + 2, att * (v.z + ee.z));
    atomicAdd(dp + 3, att * (v.w + ee.w));
}

// ---------------- relu -------------------------------------------------------
__global__ void relu_kernel(float* __restrict__ p, int n) {
    int i = blockIdx.x * blockDim.x + threadIdx.x;
    if (i < n) p[i] = fmaxf(p[i], 0.0f);
}

// ---------------- launch -----------------------------------------------------
extern "C" void kernel_launch(void* const* d_in, const int* in_sizes, int n_in,
                              void* d_out, int out_size) {
    const float* x          = (const float*)d_in[0];
    const void*  edge_index = d_in[1];
    const float* edge_feats = (const float*)d_in[2];
    const float* Wq1 = (const float*)d_in[3];
    const float* bq1 = (const float*)d_in[4];
    const float* Wk1 = (const float*)d_in[5];
    const float* bk1 = (const float*)d_in[6];
    const float* Wv1 = (const float*)d_in[7];
    const float* bv1 = (const float*)d_in[8];
    const float* We1 = (const float*)d_in[9];
    const float* Ws1 = (const float*)d_in[10];
    const float* bs1 = (const float*)d_in[11];
    const float* Wq2 = (const float*)d_in[12];
    const float* bq2 = (const float*)d_in[13];
    const float* Wk2 = (const float*)d_in[14];
    const float* bk2 = (const float*)d_in[15];
    const float* Wv2 = (const float*)d_in[16];
    const float* bv2 = (const float*)d_in[17];
    const float* We2 = (const float*)d_in[18];
    const float* Ws2 = (const float*)d_in[19];
    const float* bs2 = (const float*)d_in[20];
    float* out = (float*)d_out;

    float* Qp; cudaGetSymbolAddress((void**)&Qp, g_Q);
    float* Kp; cudaGetSymbolAddress((void**)&Kp, g_K);
    float* Vp; cudaGetSymbolAddress((void**)&Vp, g_V);
    float* Hp; cudaGetSymbolAddress((void**)&Hp, g_H);
    float* Ep; cudaGetSymbolAddress((void**)&Ep, g_E1);

    const int NGRID  = (NN + 31) / 32;          // node GEMM tiles
    const int EGRID  = EE / 32;                 // edge GEMM tiles
    const int EWGRID = (EE + 7) / 8;            // warp-per-edge, 8 warps/block
    const int ZGRID  = (NN * 8 + NN + 255) / 256;
    const int RGRID  = (NN * 128 + 255) / 256;

    // setup
    detect_idx_kernel<<<1, 256>>>((const unsigned int*)edge_index);
    extract_idx_kernel<<<(EE + 255) / 256, 256>>>(edge_index);
    zero_denoms_kernel<<<ZGRID, 256>>>();

    // ---- layer 1 ----
    gemm128_kernel<<<NGRID, 256>>>(x, Wq1, bq1, Qp, NN);
    gemm128_kernel<<<NGRID, 256>>>(x, Wk1, bk1, Kp, NN);
    gemm128_kernel<<<NGRID, 256>>>(x, Wv1, bv1, Vp, NN);
    gemm128_kernel<<<NGRID, 256>>>(x, Ws1, bs1, Hp, NN);   // skip term -> accumulator
    gemm_edge_kernel<<<EGRID, 256>>>(edge_feats, We1, Ep);
    epass1_l1_kernel<<<EWGRID, 256>>>();
    epass2_l1_kernel<<<EWGRID, 256>>>();
    relu_kernel<<<RGRID, 256>>>(Hp, NN * 128);

    // ---- layer 2 ----
    gemm128_kernel<<<NGRID, 256>>>(Hp, Wq2, bq2, Qp, NN);
    gemm128_kernel<<<NGRID, 256>>>(Hp, Wk2, bk2, Kp, NN);
    gemm128_kernel<<<NGRID, 256>>>(Hp, Wv2, bv2, Vp, NN);
    gemm128_kernel<<<NGRID, 256>>>(Hp, Ws2, bs2, out, NN); // skip term -> output accumulator
    gemm_edge_kernel<<<EGRID, 256>>>(edge_feats, We2, Ep);
    epass1_l2_kernel<<<EWGRID, 256>>>();
    epass2_l2_kernel<<<EWGRID, 256>>>(out);
    relu_kernel<<<RGRID, 256>>>(out, NN * 128);
}

// round 6
// speedup vs baseline: 1.4102x; 1.4102x over previous
#include <cuda_runtime.h>
#include <cuda_bf16.h>
#include <math.h>

// Problem constants (fixed by the reference)
#define NN 50000
#define EE 400000
// IN=128, H1=128, HEADS=8, HID=16, OUT=128, EDIM=32

// ---------------- scratch (static device globals; no allocation) -------------
static __device__ float g_Q[NN * 128];
static __device__ float g_K[NN * 128];
static __device__ float g_V[NN * 128];
static __device__ float g_S[NN * 128];          // skip term x@Ws+bs
static __device__ float g_H[NN * 128];          // layer1 output h
static __device__ int   g_src[EE];
static __device__ int   g_dst[EE];
static __device__ int   g_deg[NN];
static __device__ int   g_rowptr[NN + 1];
static __device__ int   g_cursor[NN];
static __device__ int   g_csr_src[EE];
static __device__ int   g_csr_eid[EE];
static __device__ int   g_is64;

// ---------------- dtype sniffing for edge_index ------------------------------
// Reference requests int64, but default JAX may yield int32. If the data is
// int64 (values < 50000), every odd 32-bit word is zero.
__global__ void detect_idx_kernel(const unsigned int* __restrict__ p) {
    __shared__ unsigned int sh[256];
    unsigned int acc = 0;
    for (int i = threadIdx.x; i < 4096; i += 256) acc |= p[2 * i + 1];
    sh[threadIdx.x] = acc;
    __syncthreads();
    for (int s = 128; s > 0; s >>= 1) {
        if (threadIdx.x < s) sh[threadIdx.x] |= sh[threadIdx.x + s];
        __syncthreads();
    }
    if (threadIdx.x == 0) g_is64 = (sh[0] == 0u) ? 1 : 0;
}

__global__ void extract_idx_kernel(const void* __restrict__ p) {
    int e = blockIdx.x * blockDim.x + threadIdx.x;
    if (e >= EE) return;
    if (g_is64) {
        const long long* q = (const long long*)p;
        g_src[e] = (int)q[e];
        g_dst[e] = (int)q[EE + e];
    } else {
        const int* q = (const int*)p;
        g_src[e] = q[e];
        g_dst[e] = q[EE + e];
    }
}

// ---------------- CSR build --------------------------------------------------
__global__ void zero_deg_kernel() {
    int i = blockIdx.x * blockDim.x + threadIdx.x;
    if (i < NN) g_deg[i] = 0;
}

__global__ void hist_kernel() {
    int e = blockIdx.x * blockDim.x + threadIdx.x;
    if (e < EE) atomicAdd(&g_deg[g_dst[e]], 1);
}

// single-block exclusive scan over degrees -> row_ptr + cursor
__global__ void __launch_bounds__(1024) csr_scan_kernel() {
    __shared__ int ssum[1024];
    int t = threadIdx.x;
    const int CH = (NN + 1023) / 1024; // 49
    int start = t * CH;
    int s = 0;
    for (int i = 0; i < CH; i++) {
        int idx = start + i;
        if (idx < NN) s += g_deg[idx];
    }
    ssum[t] = s;
    __syncthreads();
    for (int off = 1; off < 1024; off <<= 1) {
        int v = (t >= off) ? ssum[t - off] : 0;
        __syncthreads();
        ssum[t] += v;
        __syncthreads();
    }
    int run = (t == 0) ? 0 : ssum[t - 1];
    for (int i = 0; i < CH; i++) {
        int idx = start + i;
        if (idx < NN) {
            g_rowptr[idx] = run;
            g_cursor[idx] = run;
            run += g_deg[idx];
        }
    }
    if (t == 1023) g_rowptr[NN] = run;
}

__global__ void csr_scatter_kernel() {
    int e = blockIdx.x * blockDim.x + threadIdx.x;
    if (e >= EE) return;
    int d = g_dst[e];
    int pos = atomicAdd(&g_cursor[d], 1);
    g_csr_src[pos] = g_src[e];
    g_csr_eid[pos] = e;
}

// ---------------- fused node GEMM: 4 outputs, 128x128 tile, 8x8 per thread ---
// C_y[n,128] = A[n,128] @ W_y[128,128] + b_y   for y = 0..3 (blockIdx.y)
__global__ void __launch_bounds__(256) gemm4_kernel(
    const float* __restrict__ A, int n,
    const float* __restrict__ W0, const float* __restrict__ b0, float* __restrict__ C0,
    const float* __restrict__ W1, const float* __restrict__ b1, float* __restrict__ C1,
    const float* __restrict__ W2, const float* __restrict__ b2, float* __restrict__ C2,
    const float* __restrict__ W3, const float* __restrict__ b3, float* __restrict__ C3)
{
    const float* W; const float* bias; float* C;
    if (blockIdx.y == 0)      { W = W0; bias = b0; C = C0; }
    else if (blockIdx.y == 1) { W = W1; bias = b1; C = C1; }
    else if (blockIdx.y == 2) { W = W2; bias = b2; C = C2; }
    else                      { W = W3; bias = b3; C = C3; }

    __shared__ float As[16][132];
    __shared__ float Ws[16][132];

    int t = threadIdx.x;
    int tx = t & 15;       // col group
    int ty = t >> 4;       // row group
    int row0 = blockIdx.x * 128;

    float acc[2][2][4][4];
    {
        float bv[2][4];
#pragma unroll
        for (int cc = 0; cc < 2; cc++)
#pragma unroll
            for (int c = 0; c < 4; c++)
                bv[cc][c] = bias[tx * 4 + cc * 64 + c];
#pragma unroll
        for (int rc = 0; rc < 2; rc++)
#pragma unroll
            for (int cc = 0; cc < 2; cc++)
#pragma unroll
                for (int r = 0; r < 4; r++)
#pragma unroll
                    for (int c = 0; c < 4; c++)
                        acc[rc][cc][r][c] = bv[cc][c];
    }

    for (int kc = 0; kc < 128; kc += 16) {
#pragma unroll
        for (int i = 0; i < 2; i++) {
            int idx = t + i * 256;           // 0..511
            int r = idx >> 2;                // 0..127
            int c4 = (idx & 3) * 4;          // 0,4,8,12
            float4 av = make_float4(0.f, 0.f, 0.f, 0.f);
            int grow = row0 + r;
            if (grow < n)
                av = *reinterpret_cast<const float4*>(A + (size_t)grow * 128 + kc + c4);
            As[c4 + 0][r] = av.x;
            As[c4 + 1][r] = av.y;
            As[c4 + 2][r] = av.z;
            As[c4 + 3][r] = av.w;
        }
#pragma unroll
        for (int i = 0; i < 2; i++) {
            int idx = t + i * 256;
            int kr = idx >> 5;               // 0..15
            int c4 = (idx & 31) * 4;
            float4 wv = *reinterpret_cast<const float4*>(W + (size_t)(kc + kr) * 128 + c4);
            *reinterpret_cast<float4*>(&Ws[kr][c4]) = wv;
        }
        __syncthreads();

#pragma unroll
        for (int kk = 0; kk < 16; kk++) {
            float a[2][4], w[2][4];
            *reinterpret_cast<float4*>(a[0]) = *reinterpret_cast<float4*>(&As[kk][ty * 4]);
            *reinterpret_cast<float4*>(a[1]) = *reinterpret_cast<float4*>(&As[kk][ty * 4 + 64]);
            *reinterpret_cast<float4*>(w[0]) = *reinterpret_cast<float4*>(&Ws[kk][tx * 4]);
            *reinterpret_cast<float4*>(w[1]) = *reinterpret_cast<float4*>(&Ws[kk][tx * 4 + 64]);
#pragma unroll
            for (int rc = 0; rc < 2; rc++)
#pragma unroll
                for (int r = 0; r < 4; r++)
#pragma unroll
                    for (int cc = 0; cc < 2; cc++)
#pragma unroll
                        for (int c = 0; c < 4; c++)
                            acc[rc][cc][r][c] += a[rc][r] * w[cc][c];
        }
        __syncthreads();
    }

#pragma unroll
    for (int rc = 0; rc < 2; rc++)
#pragma unroll
        for (int r = 0; r < 4; r++) {
            int grow = row0 + ty * 4 + rc * 64 + r;
            if (grow < n) {
#pragma unroll
                for (int cc = 0; cc < 2; cc++) {
                    float4 v = make_float4(acc[rc][cc][r][0], acc[rc][cc][r][1],
                                           acc[rc][cc][r][2], acc[rc][cc][r][3]);
                    *reinterpret_cast<float4*>(C + (size_t)grow * 128 + tx * 4 + cc * 64) = v;
                }
            }
        }
}

// ---------------- fused attention gather (no edge-embedding materialization) -
// Uses linearity of ee = ef @ We:
//   alpha_h = q_h.k_h + ef . qe[:,h]    with qe[i][h] = sum_c We[i][16h+c] q[16h+c]
//   out     = (sum ea*v + (sum ea*ef) @ We) / denom + skip, relu
// warp per destination node; NH = 8 (layer1, 16ch heads) or 1 (layer2, 128ch).
template <int NH>
__global__ void __launch_bounds__(256) node_attn_kernel(
    const float* __restrict__ Q, const float* __restrict__ K, const float* __restrict__ V,
    const float* __restrict__ EF, const float* __restrict__ We,
    const float* __restrict__ SK, float* __restrict__ outp, float scale)
{
    __shared__ float We_sm[32][132];   // We[32][128], padded
    __shared__ float q_sm[8][128];
    __shared__ float wef_sm[8][288];   // [warp][lane*9 + h], NH==8 only

    int t = threadIdx.x;
    // stage We (32x128) into smem, block-wide
    for (int i = t; i < 32 * 32; i += 256) {
        int row = i >> 5, c4 = (i & 31) * 4;
        float4 wv = *reinterpret_cast<const float4*>(We + (size_t)row * 128 + c4);
        *reinterpret_cast<float4*>(&We_sm[row][c4]) = wv;
    }
    __syncthreads();

    int w = t >> 5;
    int l = t & 31;
    int n = blockIdx.x * 8 + w;
    if (n >= NN) return;

    // load q row; lane l owns cols 4l..4l+3 (head l>>2 when NH==8)
    float4 q4 = reinterpret_cast<const float4*>(Q + (size_t)n * 128)[l];
    *reinterpret_cast<float4*>(&q_sm[w][l * 4]) = q4;
    __syncwarp();

    // qe[h] = sum_c We_sm[l][16h+c] * q[16h+c]   (lane l plays role i=l)
    float qe[NH];
    if (NH == 8) {
#pragma unroll
        for (int h = 0; h < 8; h++) {
            float a = 0.f;
#pragma unroll
            for (int c = 0; c < 16; c += 4) {
                float4 wv = *reinterpret_cast<float4*>(&We_sm[l][16 * h + c]);
                float4 qv = *reinterpret_cast<float4*>(&q_sm[w][16 * h + c]);
                a += wv.x * qv.x + wv.y * qv.y + wv.z * qv.z + wv.w * qv.w;
            }
            qe[h] = a;
        }
    } else {
        float a = 0.f;
#pragma unroll
        for (int c = 0; c < 128; c += 4) {
            float4 wv = *reinterpret_cast<float4*>(&We_sm[l][c]);
            float4 qv = *reinterpret_cast<float4*>(&q_sm[w][c]);
            a += wv.x * qv.x + wv.y * qv.y + wv.z * qv.z + wv.w * qv.w;
        }
        qe[0] = a;
    }

    float4 accv = make_float4(0.f, 0.f, 0.f, 0.f);
    float wef[NH];
#pragma unroll
    for (int h = 0; h < NH; h++) wef[h] = 0.f;
    float den = 0.f;
    int hm = (NH == 8) ? (l >> 2) : 0;

    int p0 = g_rowptr[n], p1 = g_rowptr[n + 1];
    for (int p = p0; p < p1; p++) {
        int src = g_csr_src[p];
        int eid = g_csr_eid[p];
        float4 k4 = reinterpret_cast<const float4*>(K + (size_t)src * 128)[l];
        float4 v4 = reinterpret_cast<const float4*>(V + (size_t)src * 128)[l];
        float ef  = EF[(size_t)eid * 32 + l];

        float s = q4.x * k4.x + q4.y * k4.y + q4.z * k4.z + q4.w * k4.w;
        if (NH == 8) {
            s += __shfl_xor_sync(0xffffffffu, s, 1);
            s += __shfl_xor_sync(0xffffffffu, s, 2);      // per-head q.k
            float tt[8];
#pragma unroll
            for (int h = 0; h < 8; h++) tt[h] = ef * qe[h];
#pragma unroll
            for (int off = 16; off > 0; off >>= 1)
#pragma unroll
                for (int h = 0; h < 8; h++)
                    tt[h] += __shfl_xor_sync(0xffffffffu, tt[h], off);
            float ea = __expf((s + tt[hm]) * scale);
            den += ea;
            accv.x += ea * v4.x; accv.y += ea * v4.y;
            accv.z += ea * v4.z; accv.w += ea * v4.w;
#pragma unroll
            for (int h = 0; h < 8; h++) {
                float eah = __shfl_sync(0xffffffffu, ea, h * 4);
                wef[h] += eah * ef;
            }
        } else {
            s += ef * qe[0];
#pragma unroll
            for (int off = 16; off > 0; off >>= 1)
                s += __shfl_xor_sync(0xffffffffu, s, off); // full q.k + ef.qe
            float ea = __expf(s * scale);
            den += ea;
            accv.x += ea * v4.x; accv.y += ea * v4.y;
            accv.z += ea * v4.z; accv.w += ea * v4.w;
            wef[0] += ea * ef;
        }
    }

    // epilogue: out = (accv + wef @ We) / den + skip, relu
    float4 oe = make_float4(0.f, 0.f, 0.f, 0.f);
    if (NH == 8) {
#pragma unroll
        for (int h = 0; h < 8; h++) wef_sm[w][l * 9 + h] = wef[h];
        __syncwarp();
#pragma unroll 8
        for (int i = 0; i < 32; i++) {
            float wv = wef_sm[w][i * 9 + hm];
            float4 we4 = *reinterpret_cast<float4*>(&We_sm[i][l * 4]);
            oe.x += wv * we4.x; oe.y += wv * we4.y;
            oe.z += wv * we4.z; oe.w += wv * we4.w;
        }
    } else {
#pragma unroll 8
        for (int i = 0; i < 32; i++) {
            float wv = __shfl_sync(0xffffffffu, wef[0], i);
            float4 we4 = *reinterpret_cast<float4*>(&We_sm[i][l * 4]);
            oe.x += wv * we4.x; oe.y += wv * we4.y;
            oe.z += wv * we4.z; oe.w += wv * we4.w;
        }
    }

    float4 sk = reinterpret_cast<const float4*>(SK + (size_t)n * 128)[l];
    float inv = 1.f / fmaxf(den, 1e-16f);
    float4 o;
    o.x = fmaxf((accv.x + oe.x) * inv + sk.x, 0.f);
    o.y = fmaxf((accv.y + oe.y) * inv + sk.y, 0.f);
    o.z = fmaxf((accv.z + oe.z) * inv + sk.z, 0.f);
    o.w = fmaxf((accv.w + oe.w) * inv + sk.w, 0.f);
    reinterpret_cast<float4*>(outp + (size_t)n * 128)[l] = o;
}

// ---------------- launch -----------------------------------------------------
extern "C" void kernel_launch(void* const* d_in, const int* in_sizes, int n_in,
                              void* d_out, int out_size) {
    const float* x          = (const float*)d_in[0];
    const void*  edge_index = d_in[1];
    const float* edge_feats = (const float*)d_in[2];
    const float* Wq1 = (const float*)d_in[3];
    const float* bq1 = (const float*)d_in[4];
    const float* Wk1 = (const float*)d_in[5];
    const float* bk1 = (const float*)d_in[6];
    const float* Wv1 = (const float*)d_in[7];
    const float* bv1 = (const float*)d_in[8];
    const float* We1 = (const float*)d_in[9];
    const float* Ws1 = (const float*)d_in[10];
    const float* bs1 = (const float*)d_in[11];
    const float* Wq2 = (const float*)d_in[12];
    const float* bq2 = (const float*)d_in[13];
    const float* Wk2 = (const float*)d_in[14];
    const float* bk2 = (const float*)d_in[15];
    const float* Wv2 = (const float*)d_in[16];
    const float* bv2 = (const float*)d_in[17];
    const float* We2 = (const float*)d_in[18];
    const float* Ws2 = (const float*)d_in[19];
    const float* bs2 = (const float*)d_in[20];
    float* out = (float*)d_out;

    float* Qp; cudaGetSymbolAddress((void**)&Qp, g_Q);
    float* Kp; cudaGetSymbolAddress((void**)&Kp, g_K);
    float* Vp; cudaGetSymbolAddress((void**)&Vp, g_V);
    float* Sp; cudaGetSymbolAddress((void**)&Sp, g_S);
    float* Hp; cudaGetSymbolAddress((void**)&Hp, g_H);

    const int NAGRID = (NN + 7) / 8;               // warp-per-node, 8 warps/block
    dim3 g4((NN + 127) / 128, 4);

    // setup: indices + CSR
    detect_idx_kernel<<<1, 256>>>((const unsigned int*)edge_index);
    extract_idx_kernel<<<(EE + 255) / 256, 256>>>(edge_index);
    zero_deg_kernel<<<(NN + 255) / 256, 256>>>();
    hist_kernel<<<(EE + 255) / 256, 256>>>();
    csr_scan_kernel<<<1, 1024>>>();
    csr_scatter_kernel<<<(EE + 255) / 256, 256>>>();

    // ---- layer 1 ----
    gemm4_kernel<<<g4, 256>>>(x, NN,
                              Wq1, bq1, Qp,
                              Wk1, bk1, Kp,
                              Wv1, bv1, Vp,
                              Ws1, bs1, Sp);
    node_attn_kernel<8><<<NAGRID, 256>>>(Qp, Kp, Vp, edge_feats, We1, Sp, Hp, 0.25f);

    // ---- layer 2 ----
    gemm4_kernel<<<g4, 256>>>(Hp, NN,
                              Wq2, bq2, Qp,
                              Wk2, bk2, Kp,
                              Wv2, bv2, Vp,
                              Ws2, bs2, Sp);
    node_attn_kernel<1><<<NAGRID, 256>>>(Qp, Kp, Vp, edge_feats, We2, Sp, out,
                                         0.08838834764831845f);
}

// round 8
// speedup vs baseline: 1.5965x; 1.1321x over previous
#include <cuda_runtime.h>
#include <cuda_bf16.h>
#include <math.h>

// Problem constants (fixed by the reference)
#define NN 50000
#define EE 400000
// IN=128, H1=128, HEADS=8, HID=16, OUT=128, EDIM=32

typedef unsigned long long u64;

__device__ __forceinline__ u64 pack2(float lo, float hi) {
    u64 r;
    asm("mov.b64 %0, {%1, %2};" : "=l"(r) : "r"(__float_as_uint(lo)), "r"(__float_as_uint(hi)));
    return r;
}
__device__ __forceinline__ void unpack2(u64 v, float& lo, float& hi) {
    unsigned int a, b;
    asm("mov.b64 {%0, %1}, %2;" : "=r"(a), "=r"(b) : "l"(v));
    lo = __uint_as_float(a); hi = __uint_as_float(b);
}
__device__ __forceinline__ void fma2(u64& d, u64 a, u64 b) {
    asm("fma.rn.f32x2 %0, %1, %2, %3;" : "=l"(d) : "l"(a), "l"(b), "l"(d));
}

// ---------------- scratch (static device globals; no allocation) -------------
static __device__ float g_Q[NN * 128];
static __device__ float g_K[NN * 128];
static __device__ float g_V[NN * 128];
static __device__ float g_S[NN * 128];          // skip term x@Ws+bs
static __device__ float g_H[NN * 128];          // layer1 output h
static __device__ int   g_src[EE];
static __device__ int   g_dst[EE];
static __device__ int   g_deg[NN];
static __device__ int   g_rowptr[NN + 1];
static __device__ int   g_cursor[NN];
static __device__ int2  g_csr[EE];              // (src, eid)
static __device__ int   g_is64;

// ---------------- dtype sniffing for edge_index ------------------------------
__global__ void detect_idx_kernel(const unsigned int* __restrict__ p) {
    __shared__ unsigned int sh[256];
    unsigned int acc = 0;
    for (int i = threadIdx.x; i < 4096; i += 256) acc |= p[2 * i + 1];
    sh[threadIdx.x] = acc;
    __syncthreads();
    for (int s = 128; s > 0; s >>= 1) {
        if (threadIdx.x < s) sh[threadIdx.x] |= sh[threadIdx.x + s];
        __syncthreads();
    }
    if (threadIdx.x == 0) g_is64 = (sh[0] == 0u) ? 1 : 0;
}

__global__ void extract_idx_kernel(const void* __restrict__ p) {
    int e = blockIdx.x * blockDim.x + threadIdx.x;
    if (e >= EE) return;
    if (g_is64) {
        const long long* q = (const long long*)p;
        g_src[e] = (int)q[e];
        g_dst[e] = (int)q[EE + e];
    } else {
        const int* q = (const int*)p;
        g_src[e] = q[e];
        g_dst[e] = q[EE + e];
    }
}

// ---------------- CSR build --------------------------------------------------
__global__ void zero_deg_kernel() {
    int i = blockIdx.x * blockDim.x + threadIdx.x;
    if (i < NN) g_deg[i] = 0;
}

__global__ void hist_kernel() {
    int e = blockIdx.x * blockDim.x + threadIdx.x;
    if (e < EE) atomicAdd(&g_deg[g_dst[e]], 1);
}

__global__ void __launch_bounds__(1024) csr_scan_kernel() {
    __shared__ int ssum[1024];
    int t = threadIdx.x;
    const int CH = (NN + 1023) / 1024; // 49
    int start = t * CH;
    int s = 0;
    for (int i = 0; i < CH; i++) {
        int idx = start + i;
        if (idx < NN) s += g_deg[idx];
    }
    ssum[t] = s;
    __syncthreads();
    for (int off = 1; off < 1024; off <<= 1) {
        int v = (t >= off) ? ssum[t - off] : 0;
        __syncthreads();
        ssum[t] += v;
        __syncthreads();
    }
    int run = (t == 0) ? 0 : ssum[t - 1];
    for (int i = 0; i < CH; i++) {
        int idx = start + i;
        if (idx < NN) {
            g_rowptr[idx] = run;
            g_cursor[idx] = run;
            run += g_deg[idx];
        }
    }
    if (t == 1023) g_rowptr[NN] = run;
}

__global__ void csr_scatter_kernel() {
    int e = blockIdx.x * blockDim.x + threadIdx.x;
    if (e >= EE) return;
    int d = g_dst[e];
    int pos = atomicAdd(&g_cursor[d], 1);
    g_csr[pos] = make_int2(g_src[e], e);
}

// ---------------- fused node GEMM: 4 outputs, 128x128 tile -------------------
// packed f32x2 FFMA: each thread 8 rows x 8 cols (cols as 4 f32x2 pairs x 2 col-chunks)
__global__ void __launch_bounds__(256) gemm4_kernel(
    const float* __restrict__ A, int n,
    const float* __restrict__ W0, const float* __restrict__ b0, float* __restrict__ C0,
    const float* __restrict__ W1, const float* __restrict__ b1, float* __restrict__ C1,
    const float* __restrict__ W2, const float* __restrict__ b2, float* __restrict__ C2,
    const float* __restrict__ W3, const float* __restrict__ b3, float* __restrict__ C3)
{
    const float* W; const float* bias; float* C;
    if (blockIdx.y == 0)      { W = W0; bias = b0; C = C0; }
    else if (blockIdx.y == 1) { W = W1; bias = b1; C = C1; }
    else if (blockIdx.y == 2) { W = W2; bias = b2; C = C2; }
    else                      { W = W3; bias = b3; C = C3; }

    __shared__ float As[16][132];
    __shared__ float Ws[16][132];

    int t = threadIdx.x;
    int tx = t & 15;       // col group: cols tx*4..tx*4+3 and +64
    int ty = t >> 4;       // row group: rows ty*4..ty*4+3 and +64
    int row0 = blockIdx.x * 128;

    // acc[rc][cc][r][c2]: packed pair of cols (tx*4 + cc*64 + 2*c2, +1)
    u64 acc[2][2][4][2];
    {
#pragma unroll
        for (int cc = 0; cc < 2; cc++)
#pragma unroll
            for (int c2 = 0; c2 < 2; c2++) {
                u64 bp = pack2(bias[tx * 4 + cc * 64 + 2 * c2],
                               bias[tx * 4 + cc * 64 + 2 * c2 + 1]);
#pragma unroll
                for (int rc = 0; rc < 2; rc++)
#pragma unroll
                    for (int r = 0; r < 4; r++)
                        acc[rc][cc][r][c2] = bp;
            }
    }

    for (int kc = 0; kc < 128; kc += 16) {
#pragma unroll
        for (int i = 0; i < 2; i++) {
            int idx = t + i * 256;           // 0..511
            int r = idx >> 2;                // 0..127
            int c4 = (idx & 3) * 4;          // 0,4,8,12
            float4 av = make_float4(0.f, 0.f, 0.f, 0.f);
            int grow = row0 + r;
            if (grow < n)
                av = *reinterpret_cast<const float4*>(A + (size_t)grow * 128 + kc + c4);
            As[c4 + 0][r] = av.x;
            As[c4 + 1][r] = av.y;
            As[c4 + 2][r] = av.z;
            As[c4 + 3][r] = av.w;
        }
#pragma unroll
        for (int i = 0; i < 2; i++) {
            int idx = t + i * 256;
            int kr = idx >> 5;               // 0..15
            int c4 = (idx & 31) * 4;
            float4 wv = *reinterpret_cast<const float4*>(W + (size_t)(kc + kr) * 128 + c4);
            *reinterpret_cast<float4*>(&Ws[kr][c4]) = wv;
        }
        __syncthreads();

#pragma unroll
        for (int kk = 0; kk < 16; kk++) {
            float a0[4], a1[4];
            *reinterpret_cast<float4*>(a0) = *reinterpret_cast<float4*>(&As[kk][ty * 4]);
            *reinterpret_cast<float4*>(a1) = *reinterpret_cast<float4*>(&As[kk][ty * 4 + 64]);
            u64 w[2][2];
            w[0][0] = *reinterpret_cast<u64*>(&Ws[kk][tx * 4]);
            w[0][1] = *reinterpret_cast<u64*>(&Ws[kk][tx * 4 + 2]);
            w[1][0] = *reinterpret_cast<u64*>(&Ws[kk][tx * 4 + 64]);
            w[1][1] = *reinterpret_cast<u64*>(&Ws[kk][tx * 4 + 66]);
#pragma unroll
            for (int r = 0; r < 4; r++) {
                u64 ap0 = pack2(a0[r], a0[r]);
                u64 ap1 = pack2(a1[r], a1[r]);
#pragma unroll
                for (int cc = 0; cc < 2; cc++)
#pragma unroll
                    for (int c2 = 0; c2 < 2; c2++) {
                        fma2(acc[0][cc][r][c2], ap0, w[cc][c2]);
                        fma2(acc[1][cc][r][c2], ap1, w[cc][c2]);
                    }
            }
        }
        __syncthreads();
    }

#pragma unroll
    for (int rc = 0; rc < 2; rc++)
#pragma unroll
        for (int r = 0; r < 4; r++) {
            int grow = row0 + ty * 4 + rc * 64 + r;
            if (grow < n) {
#pragma unroll
                for (int cc = 0; cc < 2; cc++) {
                    float x0, x1, x2, x3;
                    unpack2(acc[rc][cc][r][0], x0, x1);
                    unpack2(acc[rc][cc][r][1], x2, x3);
                    *reinterpret_cast<float4*>(C + (size_t)grow * 128 + tx * 4 + cc * 64)
                        = make_float4(x0, x1, x2, x3);
                }
            }
        }
}

// ---------------- fused attention gather (no edge-embedding materialization) -
// alpha_h = q_h.k_h + ef . qe[:,h],  qe[i][h] = sum_c We[i][16h+c] q[16h+c]
// out = (sum ea*v + (sum ea*ef) @ We) / denom + skip, relu
// warp per destination node; NH = 8 (layer1) or 1 (layer2).
template <int NH>
__global__ void __launch_bounds__(256) node_attn_kernel(
    const float* __restrict__ Q, const float* __restrict__ K, const float* __restrict__ V,
    const float* __restrict__ EF, const float* __restrict__ We,
    const float* __restrict__ SK, float* __restrict__ outp, float scale)
{
    __shared__ float We_sm[32][132];      // We[32][128], padded
    __shared__ float wbuf[8][2][288];     // per-warp scratch (q stage / products / wef)

    int t = threadIdx.x;
    for (int i = t; i < 32 * 32; i += 256) {
        int row = i >> 5, c4 = (i & 31) * 4;
        float4 wv = *reinterpret_cast<const float4*>(We + (size_t)row * 128 + c4);
        *reinterpret_cast<float4*>(&We_sm[row][c4]) = wv;
    }
    __syncthreads();

    int w = t >> 5;
    int l = t & 31;
    int n = blockIdx.x * 8 + w;
    if (n >= NN) return;

    // stage q row into warp scratch, then compute qe (lane l plays We-row i=l)
    float4 q4 = reinterpret_cast<const float4*>(Q + (size_t)n * 128)[l];
    *reinterpret_cast<float4*>(&wbuf[w][0][l * 4]) = q4;
    __syncwarp();

    float qe[NH];
    if (NH == 8) {
#pragma unroll
        for (int h = 0; h < 8; h++) {
            float a = 0.f;
#pragma unroll
            for (int c = 0; c < 16; c += 4) {
                float4 wv = *reinterpret_cast<float4*>(&We_sm[l][16 * h + c]);
                float4 qv = *reinterpret_cast<float4*>(&wbuf[w][0][16 * h + c]);
                a += wv.x * qv.x + wv.y * qv.y + wv.z * qv.z + wv.w * qv.w;
            }
            qe[h] = a;
        }
    } else {
        float a = 0.f;
#pragma unroll
        for (int c = 0; c < 128; c += 4) {
            float4 wv = *reinterpret_cast<float4*>(&We_sm[l][c]);
            float4 qv = *reinterpret_cast<float4*>(&wbuf[w][0][c]);
            a += wv.x * qv.x + wv.y * qv.y + wv.z * qv.z + wv.w * qv.w;
        }
        qe[0] = a;
    }
    __syncwarp();

    float4 accv = make_float4(0.f, 0.f, 0.f, 0.f);
    float wef[NH];
#pragma unroll
    for (int h = 0; h < NH; h++) wef[h] = 0.f;
    float den = 0.f;
    int hm = (NH == 8) ? (l >> 2) : 0;
    int p4 = l & 3;

    int p0 = g_rowptr[n], p1 = g_rowptr[n + 1];
    for (int p = p0; p < p1; p++) {
        int2 se = g_csr[p];
        int src = se.x, eid = se.y;
        float4 k4 = reinterpret_cast<const float4*>(K + (size_t)src * 128)[l];
        float4 v4 = reinterpret_cast<const float4*>(V + (size_t)src * 128)[l];
        float ef  = EF[(size_t)eid * 32 + l];

        float s = q4.x * k4.x + q4.y * k4.y + q4.z * k4.z + q4.w * k4.w;
        if (NH == 8) {
            s += __shfl_xor_sync(0xffffffffu, s, 1);
            s += __shfl_xor_sync(0xffffffffu, s, 2);       // per-head q.k
            // products: P[i=lane][h] = ef_i * qe_i[h] via smem (double-buffered)
            float* pb = &wbuf[w][p & 1][0];
#pragma unroll
            for (int h = 0; h < 8; h++) pb[l * 9 + h] = ef * qe[h];
            __syncwarp();
            // lane (h=hm, p4) sums rows i = p4*8..p4*8+7, col hm; then 4-lane reduce
            float ts = 0.f;
#pragma unroll
            for (int j = 0; j < 8; j++) ts += pb[(p4 * 8 + j) * 9 + hm];
            ts += __shfl_xor_sync(0xffffffffu, ts, 1);
            ts += __shfl_xor_sync(0xffffffffu, ts, 2);
            float ea = __expf((s + ts) * scale);           // group-uniform
            den += ea;
            accv.x += ea * v4.x; accv.y += ea * v4.y;
            accv.z += ea * v4.z; accv.w += ea * v4.w;
#pragma unroll
            for (int h = 0; h < 8; h++) {
                float eah = __shfl_sync(0xffffffffu, ea, h * 4);
                wef[h] += eah * ef;
            }
        } else {
            s += ef * qe[0];
#pragma unroll
            for (int off = 16; off > 0; off >>= 1)
                s += __shfl_xor_sync(0xffffffffu, s, off);
            float ea = __expf(s * scale);
            den += ea;
            accv.x += ea * v4.x; accv.y += ea * v4.y;
            accv.z += ea * v4.z; accv.w += ea * v4.w;
            wef[0] += ea * ef;
        }
    }

    // epilogue: out = (accv + wef @ We) / den + skip, relu
    float4 oe = make_float4(0.f, 0.f, 0.f, 0.f);
    if (NH == 8) {
        __syncwarp();
#pragma unroll
        for (int h = 0; h < 8; h++) wbuf[w][0][l * 9 + h] = wef[h];
        __syncwarp();
#pragma unroll 8
        for (int i = 0; i < 32; i++) {
            float wv = wbuf[w][0][i * 9 + hm];
            float4 we4 = *reinterpret_cast<float4*>(&We_sm[i][l * 4]);
            oe.x += wv * we4.x; oe.y += wv * we4.y;
            oe.z += wv * we4.z; oe.w += wv * we4.w;
        }
    } else {
#pragma unroll 8
        for (int i = 0; i < 32; i++) {
            float wv = __shfl_sync(0xffffffffu, wef[0], i);
            float4 we4 = *reinterpret_cast<float4*>(&We_sm[i][l * 4]);
            oe.x += wv * we4.x; oe.y += wv * we4.y;
            oe.z += wv * we4.z; oe.w += wv * we4.w;
        }
    }

    float4 sk = reinterpret_cast<const float4*>(SK + (size_t)n * 128)[l];
    float inv = 1.f / fmaxf(den, 1e-16f);
    float4 o;
    o.x = fmaxf((accv.x + oe.x) * inv + sk.x, 0.f);
    o.y = fmaxf((accv.y + oe.y) * inv + sk.y, 0.f);
    o.z = fmaxf((accv.z + oe.z) * inv + sk.z, 0.f);
    o.w = fmaxf((accv.w + oe.w) * inv + sk.w, 0.f);
    reinterpret_cast<float4*>(outp + (size_t)n * 128)[l] = o;
}

// ---------------- launch -----------------------------------------------------
extern "C" void kernel_launch(void* const* d_in, const int* in_sizes, int n_in,
                              void* d_out, int out_size) {
    const float* x          = (const float*)d_in[0];
    const void*  edge_index = d_in[1];
    const float* edge_feats = (const float*)d_in[2];
    const float* Wq1 = (const float*)d_in[3];
    const float* bq1 = (const float*)d_in[4];
    const float* Wk1 = (const float*)d_in[5];
    const float* bk1 = (const float*)d_in[6];
    const float* Wv1 = (const float*)d_in[7];
    const float* bv1 = (const float*)d_in[8];
    const float* We1 = (const float*)d_in[9];
    const float* Ws1 = (const float*)d_in[10];
    const float* bs1 = (const float*)d_in[11];
    const float* Wq2 = (const float*)d_in[12];
    const float* bq2 = (const float*)d_in[13];
    const float* Wk2 = (const float*)d_in[14];
    const float* bk2 = (const float*)d_in[15];
    const float* Wv2 = (const float*)d_in[16];
    const float* bv2 = (const float*)d_in[17];
    const float* We2 = (const float*)d_in[18];
    const float* Ws2 = (const float*)d_in[19];
    const float* bs2 = (const float*)d_in[20];
    float* out = (float*)d_out;

    float* Qp; cudaGetSymbolAddress((void**)&Qp, g_Q);
    float* Kp; cudaGetSymbolAddress((void**)&Kp, g_K);
    float* Vp; cudaGetSymbolAddress((void**)&Vp, g_V);
    float* Sp; cudaGetSymbolAddress((void**)&Sp, g_S);
    float* Hp; cudaGetSymbolAddress((void**)&Hp, g_H);

    const int NAGRID = (NN + 7) / 8;               // warp-per-node, 8 warps/block
    dim3 g4((NN + 127) / 128, 4);

    // setup + layer-1 GEMM early (GEMM depends only on x; also puts gemm4 in the
    // ncu capture slot)
    detect_idx_kernel<<<1, 256>>>((const unsigned int*)edge_index);
    extract_idx_kernel<<<(EE + 255) / 256, 256>>>(edge_index);
    zero_deg_kernel<<<(NN + 255) / 256, 256>>>();
    gemm4_kernel<<<g4, 256>>>(x, NN,
                              Wq1, bq1, Qp,
                              Wk1, bk1, Kp,
                              Wv1, bv1, Vp,
                              Ws1, bs1, Sp);
    hist_kernel<<<(EE + 255) / 256, 256>>>();
    csr_scan_kernel<<<1, 1024>>>();
    csr_scatter_kernel<<<(EE + 255) / 256, 256>>>();

    // ---- layer 1 attention ----
    node_attn_kernel<8><<<NAGRID, 256>>>(Qp, Kp, Vp, edge_feats, We1, Sp, Hp, 0.25f);

    // ---- layer 2 ----
    gemm4_kernel<<<g4, 256>>>(Hp, NN,
                              Wq2, bq2, Qp,
                              Wk2, bk2, Kp,
                              Wv2, bv2, Vp,
                              Ws2, bs2, Sp);
    node_attn_kernel<1><<<NAGRID, 256>>>(Qp, Kp, Vp, edge_feats, We2, Sp, out,
                                         0.08838834764831845f);
}